// round 14
// baseline (speedup 1.0000x reference)
#include <cuda_runtime.h>
#include <math.h>

// ---------------- problem constants ----------------
#define BATCH   8
#define NSITES  1024
#define ZWD     8
#define ZID     32
#define KOBJ    48
#define CFD     32
#define CROPSZ  28
#define FAN     (CFD*CROPSZ*CROPSZ)   // 25088
#define MTOT    (KOBJ*BATCH)          // 384
#define WRAW    128
#define PIX     (WRAW*WRAW)           // 16384
#define SMALLF  (2*CROPSZ*CROPSZ)     // 1568
#define NSPLIT  98

// ---------------- output offsets ----------------
#define OFF_PROBMAP  0u
#define OFF_AREAMAP  8192u
#define OFF_CFEW     16384u
#define OFF_PFEW     16768u
#define OFF_BXF      17152u
#define OFF_BYF      17536u
#define OFF_BWF      17920u
#define OFF_BHF      18304u
#define OFF_BMASK    18688u
#define OFF_BMNON    6310144u
#define OFF_BIMG     12601600u
#define OFF_ZSF      18893056u
#define OFF_ZKF      18896128u
#define OFF_ZIS      18899200u
#define OFF_ZIK      18911488u

// ---------------- device scratch ----------------
__device__ float g_zs   [NSITES*BATCH*ZWD];
__device__ float g_zkl  [NSITES*BATCH*ZWD];
__device__ float g_bx   [NSITES*BATCH];
__device__ float g_by   [NSITES*BATCH];
__device__ float g_bw   [NSITES*BATCH];
__device__ float g_bh   [NSITES*BATCH];
__device__ float g_call [NSITES*BATCH];
__device__ float g_bxf  [MTOT];
__device__ float g_byf  [MTOT];
__device__ float g_bwf  [MTOT];
__device__ float g_bhf  [MTOT];
__device__ float g_cf   [MTOT];
__device__ float g_crop [MTOT*FAN];
__device__ float g_encp [NSPLIT*MTOT*64];
__device__ float g_smallw[MTOT*SMALLF];

// ---------------- helpers ----------------
__device__ __forceinline__ float sigmoidf_(float x){ return 1.0f/(1.0f+expf(-x)); }
__device__ __forceinline__ float softplusf_(float x){ return fmaxf(x,0.0f) + log1pf(expf(-fabsf(x))); }

// ================= K1 =================
__global__ void k1_site(const float* __restrict__ logit,
                        const float* __restrict__ zmu,
                        const float* __restrict__ zstd,
                        const float* __restrict__ zeps,
                        const float* __restrict__ wz,
                        const float* __restrict__ bz,
                        float* __restrict__ out)
{
    int g = blockIdx.x*blockDim.x + threadIdx.x;
    if (g >= BATCH*NSITES) return;
    int b = g >> 10;
    int n = g & 1023;

    float zs[ZWD];
    #pragma unroll
    for (int z = 0; z < ZWD; z++) {
        int idx = (b*ZWD + z)*NSITES + n;
        float mu = zmu[idx];
        float sd = zstd[idx];
        float s  = mu + sd * zeps[idx];
        float kl = 0.5f*(mu*mu + sd*sd) - logf(sd) - 0.5f;
        zs[z] = s;
        g_zs [(n*BATCH+b)*ZWD + z] = s;
        g_zkl[(n*BATCH+b)*ZWD + z] = kl;
    }

    float t[4];
    #pragma unroll
    for (int c = 0; c < 4; c++) {
        float a = __ldg(&bz[c]);
        #pragma unroll
        for (int z = 0; z < ZWD; z++) a += zs[z]*__ldg(&wz[c*ZWD+z]);
        t[c] = sigmoidf_(a);
    }
    int ix = n >> 5, iy = n & 31;
    float bx = 4.0f*((float)ix + t[0]);
    float by = 4.0f*((float)iy + t[1]);
    float bw = 10.0f + 30.0f*t[2];
    float bh = 10.0f + 30.0f*t[3];
    g_bx[n*BATCH+b] = bx;  g_by[n*BATCH+b] = by;
    g_bw[n*BATCH+b] = bw;  g_bh[n*BATCH+b] = bh;

    out[OFF_AREAMAP + b*NSITES + n] = bw*bh;
    float c0 = logit[b*NSITES + n];
    out[OFF_PROBMAP + b*NSITES + n] = sigmoidf_(c0);
    g_call[n*BATCH+b] = c0;
}

// ================= K2: one warp per batch, register top-48 =================
// keys: (orderable value bits << 32) | (0xFFFFFFFF - site index)
// -> max key = largest value, ties resolved to smallest index (jax top_k order).
__global__ void __launch_bounds__(32) k2_topk(float* __restrict__ out)
{
    int b = blockIdx.x, lane = threadIdx.x;
    unsigned long long key[32];
    #pragma unroll
    for (int r = 0; r < 32; r++) {
        int n = r*32 + lane;
        float v = g_call[n*BATCH + b];
        unsigned int f = __float_as_uint(v);
        unsigned int u = (f & 0x80000000u) ? ~f : (f | 0x80000000u);
        key[r] = ((unsigned long long)u << 32) | (unsigned long long)(0xFFFFFFFFu - (unsigned)n);
    }
    __shared__ int win[KOBJ];

    for (int kk = 0; kk < KOBJ; kk++) {
        // register tree-max with index tracking (depth 5, fully unrolled)
        unsigned long long tk[16]; int tr[16];
        #pragma unroll
        for (int r = 0; r < 16; r++) {
            bool gsel = key[r+16] > key[r];
            tk[r] = gsel ? key[r+16] : key[r];
            tr[r] = gsel ? (r+16) : r;
        }
        #pragma unroll
        for (int w = 8; w >= 1; w >>= 1) {
            #pragma unroll
            for (int r = 0; r < 8; r++) {
                if (r < w) {
                    if (tk[r+w] > tk[r]) { tk[r] = tk[r+w]; tr[r] = tr[r+w]; }
                }
            }
        }
        unsigned long long best = tk[0]; int br = tr[0];
        unsigned long long gb = best;
        #pragma unroll
        for (int o = 16; o; o >>= 1) {
            unsigned long long ob = __shfl_xor_sync(0xffffffffu, gb, o);
            if (ob > gb) gb = ob;
        }
        bool iswin = (best == gb);   // keys are unique -> exactly one winner lane
        #pragma unroll
        for (int r = 0; r < 32; r++)
            if (iswin && r == br) key[r] = 0ull;
        if (iswin) win[kk] = (int)(0xFFFFFFFFu - (unsigned)(gb & 0xFFFFFFFFull));
    }
    __syncwarp();

    for (int kk = lane; kk < KOBJ; kk += 32) {
        int n = win[kk];
        int m = kk*BATCH + b;
        float c = g_call[n*BATCH+b];
        out[OFF_CFEW + m] = c;
        out[OFF_PFEW + m] = sigmoidf_(c);
        float bx = g_bx[n*BATCH+b], by = g_by[n*BATCH+b];
        float bw = g_bw[n*BATCH+b], bh = g_bh[n*BATCH+b];
        out[OFF_BXF + m] = bx;  out[OFF_BYF + m] = by;
        out[OFF_BWF + m] = bw;  out[OFF_BHF + m] = bh;
        g_bxf[m] = bx; g_byf[m] = by; g_bwf[m] = bw; g_bhf[m] = bh;
        g_cf[m] = c;
        #pragma unroll
        for (int z = 0; z < ZWD; z++) {
            out[OFF_ZSF + m*ZWD + z] = g_zs [(n*BATCH+b)*ZWD + z];
            out[OFF_ZKF + m*ZWD + z] = g_zkl[(n*BATCH+b)*ZWD + z];
        }
    }
}

// ================= K3: bilinear crop -> g_crop =================
__global__ void __launch_bounds__(256) k3_crop(const float* __restrict__ feat)
{
    int m = blockIdx.x;
    int b = m & 7;
    int t = threadIdx.x;
    __shared__ int   si0[784], si1[784], si2[784], si3[784];
    __shared__ float sw0[784], sw1[784], sw2[784], sw3[784];

    float bx = g_bxf[m], bw = g_bwf[m];
    float by = g_byf[m], bh = g_bhf[m];

    for (int pos = t; pos < 784; pos += 256) {
        int i = pos / 28, j = pos - (pos/28)*28;
        float u = ((float)i + 0.5f) / 28.0f;
        float vv= ((float)j + 0.5f) / 28.0f;
        float x = bx + (u - 0.5f)*bw - 0.5f;
        float y = by + (vv- 0.5f)*bh - 0.5f;
        float x0f = floorf(x), y0f = floorf(y);
        int x0 = (int)x0f, y0 = (int)y0f;
        float wx1 = x - x0f, wy1 = y - y0f;
        float wx0 = 1.0f - wx1, wy0 = 1.0f - wy1;
        bool xa = (x0   >= 0 && x0   < WRAW);
        bool xb = (x0+1 >= 0 && x0+1 < WRAW);
        bool ya = (y0   >= 0 && y0   < WRAW);
        bool yb = (y0+1 >= 0 && y0+1 < WRAW);
        int cx0 = min(max(x0,   0), WRAW-1);
        int cx1 = min(max(x0+1, 0), WRAW-1);
        int cy0 = min(max(y0,   0), WRAW-1);
        int cy1 = min(max(y0+1, 0), WRAW-1);
        si0[pos] = cx0*WRAW + cy0;  sw0[pos] = (xa&&ya) ? wx0*wy0 : 0.0f;
        si1[pos] = cx1*WRAW + cy0;  sw1[pos] = (xb&&ya) ? wx1*wy0 : 0.0f;
        si2[pos] = cx0*WRAW + cy1;  sw2[pos] = (xa&&yb) ? wx0*wy1 : 0.0f;
        si3[pos] = cx1*WRAW + cy1;  sw3[pos] = (xb&&yb) ? wx1*wy1 : 0.0f;
    }
    __syncthreads();

    const float* fb = feat + (size_t)b*CFD*PIX;
    float* dst = &g_crop[(size_t)m*FAN];
    #pragma unroll 2
    for (int c = 0; c < CFD; c++) {
        const float* img = fb + c*PIX;
        for (int pos = t; pos < 784; pos += 256) {
            float v = sw0[pos]*__ldg(&img[si0[pos]])
                    + sw1[pos]*__ldg(&img[si1[pos]])
                    + sw2[pos]*__ldg(&img[si2[pos]])
                    + sw3[pos]*__ldg(&img[si3[pos]]);
            dst[c*784 + pos] = v;
        }
    }
}

// ================= K4: enc GEMM, double-buffered single-sync pipeline ==========
// (A reads are SCALAR: ASTR=33 is odd, so vector loads on odd rows would be
//  misaligned — that was the R12 crash. Scalar LDS at stride 33 is conflict-free.)
#define KT4   32
#define KITER 8
#define ASTR  33
#define AS_FLOATS (128*ASTR)        // 4224
#define BS_FLOATS (KT4*64)          // 2048
#define K4_SMEM ((2*AS_FLOATS + 2*BS_FLOATS)*4)   // 50176 bytes
__global__ void __launch_bounds__(256,2) k4_gemm(const float* __restrict__ wenc)
{
    extern __shared__ float smem[];
    int t = threadIdx.x;
    int mbase = blockIdx.x * 128;
    int kb0   = blockIdx.y * (KITER*KT4);
    int m0 = (t >> 3) * 4;
    int n0 = (t & 7) * 8;
    int ldm = t >> 3;
    int ldk = (t & 7) * 4;
    int dB  = t & 63;
    int kqB = (t >> 6) * 8;

    float acc[4][8];
    #pragma unroll
    for (int i = 0; i < 4; i++)
        #pragma unroll
        for (int j = 0; j < 8; j++) acc[i][j] = 0.0f;

    float4 ra[4], rb0, rb1;
    #pragma unroll
    for (int p = 0; p < 4; p++)
        ra[p] = *(const float4*)&g_crop[(size_t)(mbase + p*32 + ldm)*FAN + kb0 + ldk];
    rb0 = *(const float4*)&wenc[(size_t)dB*FAN + kb0 + kqB];
    rb1 = *(const float4*)&wenc[(size_t)dB*FAN + kb0 + kqB + 4];

    for (int it = 0; it < KITER; it++) {
        float* Asb = smem + (it & 1)*AS_FLOATS;
        float* Bsb = smem + 2*AS_FLOATS + (it & 1)*BS_FLOATS;

        // stage current tile (buffer parity makes this safe vs. other warps'
        // compute of it-1, which reads the opposite buffer)
        #pragma unroll
        for (int p = 0; p < 4; p++) {
            int mm = p*32 + ldm;
            Asb[mm*ASTR + ldk+0] = ra[p].x;
            Asb[mm*ASTR + ldk+1] = ra[p].y;
            Asb[mm*ASTR + ldk+2] = ra[p].z;
            Asb[mm*ASTR + ldk+3] = ra[p].w;
        }
        Bsb[(kqB+0)*64 + dB] = rb0.x;
        Bsb[(kqB+1)*64 + dB] = rb0.y;
        Bsb[(kqB+2)*64 + dB] = rb0.z;
        Bsb[(kqB+3)*64 + dB] = rb0.w;
        Bsb[(kqB+4)*64 + dB] = rb1.x;
        Bsb[(kqB+5)*64 + dB] = rb1.y;
        Bsb[(kqB+6)*64 + dB] = rb1.z;
        Bsb[(kqB+7)*64 + dB] = rb1.w;

        // prefetch next tile (latency hidden by the compute below)
        if (it + 1 < KITER) {
            int kb = kb0 + (it+1)*KT4;
            #pragma unroll
            for (int p = 0; p < 4; p++)
                ra[p] = *(const float4*)&g_crop[(size_t)(mbase + p*32 + ldm)*FAN + kb + ldk];
            rb0 = *(const float4*)&wenc[(size_t)dB*FAN + kb + kqB];
            rb1 = *(const float4*)&wenc[(size_t)dB*FAN + kb + kqB + 4];
        }

        __syncthreads();   // single barrier per iteration

        #pragma unroll 8
        for (int kk = 0; kk < KT4; kk++) {
            float a0 = Asb[(m0+0)*ASTR + kk];
            float a1 = Asb[(m0+1)*ASTR + kk];
            float a2 = Asb[(m0+2)*ASTR + kk];
            float a3 = Asb[(m0+3)*ASTR + kk];
            float4 b0 = *(const float4*)&Bsb[kk*64 + n0];
            float4 b1 = *(const float4*)&Bsb[kk*64 + n0 + 4];
            acc[0][0] += a0*b0.x; acc[0][1] += a0*b0.y; acc[0][2] += a0*b0.z; acc[0][3] += a0*b0.w;
            acc[0][4] += a0*b1.x; acc[0][5] += a0*b1.y; acc[0][6] += a0*b1.z; acc[0][7] += a0*b1.w;
            acc[1][0] += a1*b0.x; acc[1][1] += a1*b0.y; acc[1][2] += a1*b0.z; acc[1][3] += a1*b0.w;
            acc[1][4] += a1*b1.x; acc[1][5] += a1*b1.y; acc[1][6] += a1*b1.z; acc[1][7] += a1*b1.w;
            acc[2][0] += a2*b0.x; acc[2][1] += a2*b0.y; acc[2][2] += a2*b0.z; acc[2][3] += a2*b0.w;
            acc[2][4] += a2*b1.x; acc[2][5] += a2*b1.y; acc[2][6] += a2*b1.z; acc[2][7] += a2*b1.w;
            acc[3][0] += a3*b0.x; acc[3][1] += a3*b0.y; acc[3][2] += a3*b0.z; acc[3][3] += a3*b0.w;
            acc[3][4] += a3*b1.x; acc[3][5] += a3*b1.y; acc[3][6] += a3*b1.z; acc[3][7] += a3*b1.w;
        }
    }

    size_t pbase = ((size_t)blockIdx.y*MTOT + mbase + m0)*64 + n0;
    #pragma unroll
    for (int i = 0; i < 4; i++) {
        float4 w0 = make_float4(acc[i][0], acc[i][1], acc[i][2], acc[i][3]);
        float4 w1 = make_float4(acc[i][4], acc[i][5], acc[i][6], acc[i][7]);
        *(float4*)&g_encp[pbase + (size_t)i*64]     = w0;
        *(float4*)&g_encp[pbase + (size_t)i*64 + 4] = w1;
    }
}

// ================= K5 =================
__global__ void k5_zi_dec(const float* __restrict__ epszi,
                          const float* __restrict__ wdec,
                          const float* __restrict__ bdec,
                          const float* __restrict__ benc,
                          float* __restrict__ out)
{
    int m = blockIdx.x, t = threadIdx.x;
    __shared__ float zsh[ZID];
    __shared__ float ench[64];
    __shared__ float red[4][64];
    {
        int c = t & 63, part = t >> 6;
        float s = 0.0f;
        int lo = part*24 + min(part,2);   // 25,25,24,24 split of 98
        int hi = lo + ((part < 2) ? 25 : 24);
        for (int sp = lo; sp < hi; sp++)
            s += g_encp[((size_t)sp*MTOT + m)*64 + c];
        red[part][c] = s;
    }
    __syncthreads();
    if (t < 64) ench[t] = benc[t] + red[0][t] + red[1][t] + red[2][t] + red[3][t];
    __syncthreads();
    if (t < ZID) {
        float mu = ench[t];
        float sp = ench[32 + t];
        float sd = softplusf_(sp) + 1e-4f;
        float s  = mu + sd * epszi[m*ZID + t];
        float kl = 0.5f*(mu*mu + sd*sd) - logf(sd) - 0.5f;
        out[OFF_ZIS + m*ZID + t] = s;
        out[OFF_ZIK + m*ZID + t] = kl;
        zsh[t] = s;
    }
    __syncthreads();
    float cf = g_cf[m];
    for (int f = t; f < SMALLF; f += 256) {
        const float4* wr = (const float4*)(wdec + (size_t)f*ZID);
        float acc = bdec[f];
        #pragma unroll
        for (int q = 0; q < 8; q++) {
            float4 w4 = wr[q];
            acc += w4.x*zsh[q*4+0] + w4.y*zsh[q*4+1]
                 + w4.z*zsh[q*4+2] + w4.w*zsh[q*4+3];
        }
        float r = (f < 784) ? softplusf_(acc) : sigmoidf_(acc);
        g_smallw[m*SMALLF + f] = r * cf;
    }
}

// ================= K67: fused uncrop + k-reduction (sparse tanh) =================
__global__ void __launch_bounds__(256) k67_all(float* __restrict__ out)
{
    int blk = blockIdx.x;
    int b = blk >> 6;
    int tile = blk & 63;
    int t = threadIdx.x;
    __shared__ float ssx[KOBJ], sox[KOBJ], ssy[KOBJ], soy[KOBJ];
    if (t < KOBJ) {
        int m = t*BATCH + b;
        float bx = g_bxf[m], bw = g_bwf[m];
        float by = g_byf[m], bh = g_bhf[m];
        float sx = 28.0f / bw;
        float sy = 28.0f / bh;
        ssx[t] = sx;  sox[t] = (0.5f - bx + 0.5f*bw)*sx - 0.5f;
        ssy[t] = sy;  soy[t] = (0.5f - by + 0.5f*bh)*sy - 0.5f;
    }
    __syncthreads();

    int p = tile*256 + t;
    float Xf = (float)(p >> 7);
    float Yf = (float)(p & 127);

    float v[KOBJ];
    float s = 0.0f;
    #pragma unroll
    for (int k = 0; k < KOBJ; k++) {
        float x = Xf*ssx[k] + sox[k];
        float y = Yf*ssy[k] + soy[k];
        float w = 0.0f, im = 0.0f, tw = 0.0f;
        if (x > -1.0f && x < 28.0f && y > -1.0f && y < 28.0f) {
            float x0f = floorf(x), y0f = floorf(y);
            int x0 = (int)x0f, y0 = (int)y0f;
            float wx1 = x - x0f, wy1 = y - y0f;
            float wx0 = 1.0f - wx1, wy0 = 1.0f - wy1;
            bool xa = (x0 >= 0), xb = (x0+1 < 28);
            bool ya = (y0 >= 0), yb = (y0+1 < 28);
            float w00 = (xa&&ya) ? wx0*wy0 : 0.0f;
            float w10 = (xb&&ya) ? wx1*wy0 : 0.0f;
            float w01 = (xa&&yb) ? wx0*wy1 : 0.0f;
            float w11 = (xb&&yb) ? wx1*wy1 : 0.0f;
            const float* img = &g_smallw[(size_t)(k*BATCH+b)*SMALLF];
            int ix0 = min(max(x0,  0),27), ix1 = min(max(x0+1,0),27);
            int iy0 = min(max(y0,  0),27), iy1 = min(max(y0+1,0),27);
            int a00 = ix0*28+iy0, a10 = ix1*28+iy0, a01 = ix0*28+iy1, a11 = ix1*28+iy1;
            w  = w00*__ldg(&img[a00])     + w10*__ldg(&img[a10])
               + w01*__ldg(&img[a01])     + w11*__ldg(&img[a11]);
            im = w00*__ldg(&img[784+a00]) + w10*__ldg(&img[784+a10])
               + w01*__ldg(&img[784+a01]) + w11*__ldg(&img[784+a11]);
            tw = tanhf(w);
        }
        v[k] = w;
        s += w;
        out[OFF_BMNON + (size_t)(k*BATCH+b)*PIX + p] = tw;
        out[OFF_BIMG  + (size_t)(k*BATCH+b)*PIX + p] = im;
    }
    float ts = tanhf(s);
    float inv = 1.0f / fmaxf(s, 1e-6f);
    float f = ts * inv;
    #pragma unroll
    for (int k = 0; k < KOBJ; k++)
        out[OFF_BMASK + (size_t)(k*BATCH+b)*PIX + p] = v[k] * f;
}

// ================= launcher =================
extern "C" void kernel_launch(void* const* d_in, const int* in_sizes, int n_in,
                              void* d_out, int out_size)
{
    const float* logit = (const float*)d_in[0];
    const float* zmu   = (const float*)d_in[1];
    const float* zstd  = (const float*)d_in[2];
    const float* zeps  = (const float*)d_in[3];
    const float* epszi = (const float*)d_in[4];
    const float* feat  = (const float*)d_in[5];
    const float* wz    = (const float*)d_in[6];
    const float* bz    = (const float*)d_in[7];
    const float* wenc  = (const float*)d_in[8];
    const float* benc  = (const float*)d_in[9];
    const float* wdec  = (const float*)d_in[10];
    const float* bdec  = (const float*)d_in[11];
    float* out = (float*)d_out;

    cudaFuncSetAttribute(k4_gemm, cudaFuncAttributeMaxDynamicSharedMemorySize, K4_SMEM);

    k1_site<<<32, 256>>>(logit, zmu, zstd, zeps, wz, bz, out);
    k2_topk<<<BATCH, 32>>>(out);
    k3_crop<<<MTOT, 256>>>(feat);
    dim3 g4(3, NSPLIT);
    k4_gemm<<<g4, 256, K4_SMEM>>>(wenc);
    k5_zi_dec<<<MTOT, 256>>>(epszi, wdec, bdec, benc, out);
    k67_all<<<BATCH*64, 256>>>(out);
}

// round 15
// speedup vs baseline: 1.0883x; 1.0883x over previous
#include <cuda_runtime.h>
#include <math.h>

// ---------------- problem constants ----------------
#define BATCH   8
#define NSITES  1024
#define ZWD     8
#define ZID     32
#define KOBJ    48
#define CFD     32
#define CROPSZ  28
#define FAN     (CFD*CROPSZ*CROPSZ)   // 25088
#define MTOT    (KOBJ*BATCH)          // 384
#define WRAW    128
#define PIX     (WRAW*WRAW)           // 16384
#define SMALLF  (2*CROPSZ*CROPSZ)     // 1568
#define NSPLIT  98

// ---------------- output offsets ----------------
#define OFF_PROBMAP  0u
#define OFF_AREAMAP  8192u
#define OFF_CFEW     16384u
#define OFF_PFEW     16768u
#define OFF_BXF      17152u
#define OFF_BYF      17536u
#define OFF_BWF      17920u
#define OFF_BHF      18304u
#define OFF_BMASK    18688u
#define OFF_BMNON    6310144u
#define OFF_BIMG     12601600u
#define OFF_ZSF      18893056u
#define OFF_ZKF      18896128u
#define OFF_ZIS      18899200u
#define OFF_ZIK      18911488u

// ---------------- device scratch ----------------
__device__ float g_zs   [NSITES*BATCH*ZWD];
__device__ float g_zkl  [NSITES*BATCH*ZWD];
__device__ float g_bx   [NSITES*BATCH];
__device__ float g_by   [NSITES*BATCH];
__device__ float g_bw   [NSITES*BATCH];
__device__ float g_bh   [NSITES*BATCH];
__device__ float g_call [NSITES*BATCH];
__device__ float g_bxf  [MTOT];
__device__ float g_byf  [MTOT];
__device__ float g_bwf  [MTOT];
__device__ float g_bhf  [MTOT];
__device__ float g_cf   [MTOT];
__device__ float g_encp [NSPLIT*MTOT*64];
__device__ float g_smallw[MTOT*SMALLF];

// ---------------- helpers ----------------
__device__ __forceinline__ float sigmoidf_(float x){ return 1.0f/(1.0f+expf(-x)); }
__device__ __forceinline__ float softplusf_(float x){ return fmaxf(x,0.0f) + log1pf(expf(-fabsf(x))); }

// ================= K1 =================
__global__ void k1_site(const float* __restrict__ logit,
                        const float* __restrict__ zmu,
                        const float* __restrict__ zstd,
                        const float* __restrict__ zeps,
                        const float* __restrict__ wz,
                        const float* __restrict__ bz,
                        float* __restrict__ out)
{
    int g = blockIdx.x*blockDim.x + threadIdx.x;
    if (g >= BATCH*NSITES) return;
    int b = g >> 10;
    int n = g & 1023;

    float zs[ZWD];
    #pragma unroll
    for (int z = 0; z < ZWD; z++) {
        int idx = (b*ZWD + z)*NSITES + n;
        float mu = zmu[idx];
        float sd = zstd[idx];
        float s  = mu + sd * zeps[idx];
        float kl = 0.5f*(mu*mu + sd*sd) - logf(sd) - 0.5f;
        zs[z] = s;
        g_zs [(n*BATCH+b)*ZWD + z] = s;
        g_zkl[(n*BATCH+b)*ZWD + z] = kl;
    }

    float t[4];
    #pragma unroll
    for (int c = 0; c < 4; c++) {
        float a = __ldg(&bz[c]);
        #pragma unroll
        for (int z = 0; z < ZWD; z++) a += zs[z]*__ldg(&wz[c*ZWD+z]);
        t[c] = sigmoidf_(a);
    }
    int ix = n >> 5, iy = n & 31;
    float bx = 4.0f*((float)ix + t[0]);
    float by = 4.0f*((float)iy + t[1]);
    float bw = 10.0f + 30.0f*t[2];
    float bh = 10.0f + 30.0f*t[3];
    g_bx[n*BATCH+b] = bx;  g_by[n*BATCH+b] = by;
    g_bw[n*BATCH+b] = bw;  g_bh[n*BATCH+b] = bh;

    out[OFF_AREAMAP + b*NSITES + n] = bw*bh;
    float c0 = logit[b*NSITES + n];
    out[OFF_PROBMAP + b*NSITES + n] = sigmoidf_(c0);
    g_call[n*BATCH+b] = c0;
}

// ================= K2: one warp per batch, register top-48 =================
__global__ void __launch_bounds__(32) k2_topk(float* __restrict__ out)
{
    int b = blockIdx.x, lane = threadIdx.x;
    unsigned long long key[32];
    #pragma unroll
    for (int r = 0; r < 32; r++) {
        int n = r*32 + lane;
        float v = g_call[n*BATCH + b];
        unsigned int f = __float_as_uint(v);
        unsigned int u = (f & 0x80000000u) ? ~f : (f | 0x80000000u);
        key[r] = ((unsigned long long)u << 32) | (unsigned long long)(0xFFFFFFFFu - (unsigned)n);
    }
    __shared__ int win[KOBJ];

    for (int kk = 0; kk < KOBJ; kk++) {
        unsigned long long tk[16]; int tr[16];
        #pragma unroll
        for (int r = 0; r < 16; r++) {
            bool gsel = key[r+16] > key[r];
            tk[r] = gsel ? key[r+16] : key[r];
            tr[r] = gsel ? (r+16) : r;
        }
        #pragma unroll
        for (int w = 8; w >= 1; w >>= 1) {
            #pragma unroll
            for (int r = 0; r < 8; r++) {
                if (r < w) {
                    if (tk[r+w] > tk[r]) { tk[r] = tk[r+w]; tr[r] = tr[r+w]; }
                }
            }
        }
        unsigned long long best = tk[0]; int br = tr[0];
        unsigned long long gb = best;
        #pragma unroll
        for (int o = 16; o; o >>= 1) {
            unsigned long long ob = __shfl_xor_sync(0xffffffffu, gb, o);
            if (ob > gb) gb = ob;
        }
        bool iswin = (best == gb);
        #pragma unroll
        for (int r = 0; r < 32; r++)
            if (iswin && r == br) key[r] = 0ull;
        if (iswin) win[kk] = (int)(0xFFFFFFFFu - (unsigned)(gb & 0xFFFFFFFFull));
    }
    __syncwarp();

    for (int kk = lane; kk < KOBJ; kk += 32) {
        int n = win[kk];
        int m = kk*BATCH + b;
        float c = g_call[n*BATCH+b];
        out[OFF_CFEW + m] = c;
        out[OFF_PFEW + m] = sigmoidf_(c);
        float bx = g_bx[n*BATCH+b], by = g_by[n*BATCH+b];
        float bw = g_bw[n*BATCH+b], bh = g_bh[n*BATCH+b];
        out[OFF_BXF + m] = bx;  out[OFF_BYF + m] = by;
        out[OFF_BWF + m] = bw;  out[OFF_BHF + m] = bh;
        g_bxf[m] = bx; g_byf[m] = by; g_bwf[m] = bw; g_bhf[m] = bh;
        g_cf[m] = c;
        #pragma unroll
        for (int z = 0; z < ZWD; z++) {
            out[OFF_ZSF + m*ZWD + z] = g_zs [(n*BATCH+b)*ZWD + z];
            out[OFF_ZKF + m*ZWD + z] = g_zkl[(n*BATCH+b)*ZWD + z];
        }
    }
}

// ================= K4: FUSED crop + enc GEMM ==========
// grid (3, 98): M tile 128, K split 256 (8 iters x 32). The crop value
// A[m][k] (k = c*784 + i*28 + j) is bilinearly sampled from feat during
// staging — g_crop round-trip (77MB) eliminated.
// Lane mapping: thread covers k = kb + (t&7) + 8e so warp-gather lanes
// have consecutive j (k3-like coalescing).
#define KT4   32
#define KITER 8
#define ASTR  33
#define AS_FLOATS (128*ASTR)                 // 4224
#define BS_FLOATS (KT4*64)                   // 2048
#define SM_WY   (2*AS_FLOATS + 2*BS_FLOATS)  // float2 wy[128*28] after buffers
#define SM_Y0   (SM_WY + 2*128*28)           // int y0[128*28]
#define K4_SMEM ((SM_Y0 + 128*28)*4)         // 93184 bytes
__global__ void __launch_bounds__(256,2) k4_fused(const float* __restrict__ feat,
                                                  const float* __restrict__ wenc)
{
    extern __shared__ float smem[];
    float2* wyt = (float2*)(smem + SM_WY);
    int*    y0t = (int*)(smem + SM_Y0);
    int t = threadIdx.x;
    int mbase = blockIdx.x * 128;
    int kb0   = blockIdx.y * (KITER*KT4);

    // ---- y-direction bilinear table, once per block ----
    for (int e = t; e < 128*28; e += 256) {
        int row = e / 28;
        int j   = e - row*28;
        int m = mbase + row;
        float by = g_byf[m], bh = g_bhf[m];
        float v = ((float)j + 0.5f) / 28.0f;
        float y = by + (v - 0.5f)*bh - 0.5f;
        float y0f = floorf(y);
        int y0 = (int)y0f;
        float wy1 = y - y0f, wy0 = 1.0f - wy1;
        bool ya = (y0   >= 0 && y0   < WRAW);
        bool yb = (y0+1 >= 0 && y0+1 < WRAW);
        wyt[e] = make_float2(ya ? wy0 : 0.0f, yb ? wy1 : 0.0f);
        y0t[e] = y0;                      // RAW y0; clamp both corners later
    }

    int mm8 = t >> 3;          // 0..31
    int qb  = t & 7;           // 0..7  (k = kb + qb + 8e)
    int m0 = (t >> 3) * 4;     // FMA fragment coords (as before)
    int n0 = (t & 7) * 8;
    int dB  = t & 63;
    int kqB = (t >> 6) * 8;

    // per-thread x-direction box params for its 4 rows
    float bxc[4], bwp[4];
    const float* basep[4];
    #pragma unroll
    for (int p = 0; p < 4; p++) {
        int m = mbase + p*32 + mm8;
        float bx = g_bxf[m], bw = g_bwf[m];
        bxc[p] = bx - 0.5f*bw - 0.5f;
        bwp[p] = bw;
        basep[p] = feat + (size_t)(m & 7)*CFD*PIX;
    }

    float acc[4][8];
    #pragma unroll
    for (int i = 0; i < 4; i++)
        #pragma unroll
        for (int j = 0; j < 8; j++) acc[i][j] = 0.0f;

    __syncthreads();   // y-table ready

    for (int it = 0; it < KITER; it++) {
        float* Asb = smem + (it & 1)*AS_FLOATS;
        float* Bsb = smem + 2*AS_FLOATS + (it & 1)*BS_FLOATS;
        int kb = kb0 + it*KT4;

        // decode this thread's 4 k-values (strided by 8)
        float ue[4]; int je[4], koff[4];
        #pragma unroll
        for (int e = 0; e < 4; e++) {
            int k = kb + qb + 8*e;
            int c = k / 784;
            int pos = k - c*784;
            int i = pos / 28;
            je[e] = pos - i*28;
            ue[e] = ((float)i + 0.5f) / 28.0f;
            koff[e] = c * PIX;
        }

        // ---- stage A: bilinear-sample 4 rows x 4 k ----
        #pragma unroll
        for (int p = 0; p < 4; p++) {
            int row = p*32 + mm8;
            #pragma unroll
            for (int e = 0; e < 4; e++) {
                float x = bxc[p] + ue[e]*bwp[p];
                float x0f = floorf(x);
                int x0 = (int)x0f;
                float wx1 = x - x0f, wx0 = 1.0f - wx1;
                float wx0z = (x0   >= 0 && x0   < WRAW) ? wx0 : 0.0f;
                float wx1z = (x0+1 >= 0 && x0+1 < WRAW) ? wx1 : 0.0f;
                int x0c = min(max(x0,   0), WRAW-1);
                int x1c = min(max(x0+1, 0), WRAW-1);
                int yi = row*28 + je[e];
                float2 wyv = wyt[yi];
                int y0r = y0t[yi];
                int y0c = min(max(y0r,   0), WRAW-1);
                int y1c = min(max(y0r+1, 0), WRAW-1);
                const float* pl = basep[p] + koff[e];
                float p00 = __ldg(&pl[x0c*WRAW + y0c]);
                float p01 = __ldg(&pl[x0c*WRAW + y1c]);
                float p10 = __ldg(&pl[x1c*WRAW + y0c]);
                float p11 = __ldg(&pl[x1c*WRAW + y1c]);
                float val = wx0z*(wyv.x*p00 + wyv.y*p01)
                          + wx1z*(wyv.x*p10 + wyv.y*p11);
                Asb[row*ASTR + qb + 8*e] = val;
            }
        }

        // ---- stage B (coalesced) ----
        {
            const float* wrow = wenc + (size_t)dB*FAN + kb + kqB;
            float4 rb0 = *(const float4*)&wrow[0];
            float4 rb1 = *(const float4*)&wrow[4];
            Bsb[(kqB+0)*64 + dB] = rb0.x;
            Bsb[(kqB+1)*64 + dB] = rb0.y;
            Bsb[(kqB+2)*64 + dB] = rb0.z;
            Bsb[(kqB+3)*64 + dB] = rb0.w;
            Bsb[(kqB+4)*64 + dB] = rb1.x;
            Bsb[(kqB+5)*64 + dB] = rb1.y;
            Bsb[(kqB+6)*64 + dB] = rb1.z;
            Bsb[(kqB+7)*64 + dB] = rb1.w;
        }

        __syncthreads();   // single barrier per iteration (buffer parity)

        #pragma unroll 8
        for (int kk = 0; kk < KT4; kk++) {
            float a0 = Asb[(m0+0)*ASTR + kk];
            float a1 = Asb[(m0+1)*ASTR + kk];
            float a2 = Asb[(m0+2)*ASTR + kk];
            float a3 = Asb[(m0+3)*ASTR + kk];
            float4 b0 = *(const float4*)&Bsb[kk*64 + n0];
            float4 b1 = *(const float4*)&Bsb[kk*64 + n0 + 4];
            acc[0][0] += a0*b0.x; acc[0][1] += a0*b0.y; acc[0][2] += a0*b0.z; acc[0][3] += a0*b0.w;
            acc[0][4] += a0*b1.x; acc[0][5] += a0*b1.y; acc[0][6] += a0*b1.z; acc[0][7] += a0*b1.w;
            acc[1][0] += a1*b0.x; acc[1][1] += a1*b0.y; acc[1][2] += a1*b0.z; acc[1][3] += a1*b0.w;
            acc[1][4] += a1*b1.x; acc[1][5] += a1*b1.y; acc[1][6] += a1*b1.z; acc[1][7] += a1*b1.w;
            acc[2][0] += a2*b0.x; acc[2][1] += a2*b0.y; acc[2][2] += a2*b0.z; acc[2][3] += a2*b0.w;
            acc[2][4] += a2*b1.x; acc[2][5] += a2*b1.y; acc[2][6] += a2*b1.z; acc[2][7] += a2*b1.w;
            acc[3][0] += a3*b0.x; acc[3][1] += a3*b0.y; acc[3][2] += a3*b0.z; acc[3][3] += a3*b0.w;
            acc[3][4] += a3*b1.x; acc[3][5] += a3*b1.y; acc[3][6] += a3*b1.z; acc[3][7] += a3*b1.w;
        }
    }

    size_t pbase = ((size_t)blockIdx.y*MTOT + mbase + m0)*64 + n0;
    #pragma unroll
    for (int i = 0; i < 4; i++) {
        float4 w0 = make_float4(acc[i][0], acc[i][1], acc[i][2], acc[i][3]);
        float4 w1 = make_float4(acc[i][4], acc[i][5], acc[i][6], acc[i][7]);
        *(float4*)&g_encp[pbase + (size_t)i*64]     = w0;
        *(float4*)&g_encp[pbase + (size_t)i*64 + 4] = w1;
    }
}

// ================= K5 =================
__global__ void k5_zi_dec(const float* __restrict__ epszi,
                          const float* __restrict__ wdec,
                          const float* __restrict__ bdec,
                          const float* __restrict__ benc,
                          float* __restrict__ out)
{
    int m = blockIdx.x, t = threadIdx.x;
    __shared__ float zsh[ZID];
    __shared__ float ench[64];
    __shared__ float red[4][64];
    {
        int c = t & 63, part = t >> 6;
        float s = 0.0f;
        int lo = part*24 + min(part,2);   // 25,25,24,24 split of 98
        int hi = lo + ((part < 2) ? 25 : 24);
        for (int sp = lo; sp < hi; sp++)
            s += g_encp[((size_t)sp*MTOT + m)*64 + c];
        red[part][c] = s;
    }
    __syncthreads();
    if (t < 64) ench[t] = benc[t] + red[0][t] + red[1][t] + red[2][t] + red[3][t];
    __syncthreads();
    if (t < ZID) {
        float mu = ench[t];
        float sp = ench[32 + t];
        float sd = softplusf_(sp) + 1e-4f;
        float s  = mu + sd * epszi[m*ZID + t];
        float kl = 0.5f*(mu*mu + sd*sd) - logf(sd) - 0.5f;
        out[OFF_ZIS + m*ZID + t] = s;
        out[OFF_ZIK + m*ZID + t] = kl;
        zsh[t] = s;
    }
    __syncthreads();
    float cf = g_cf[m];
    for (int f = t; f < SMALLF; f += 256) {
        const float4* wr = (const float4*)(wdec + (size_t)f*ZID);
        float acc = bdec[f];
        #pragma unroll
        for (int q = 0; q < 8; q++) {
            float4 w4 = wr[q];
            acc += w4.x*zsh[q*4+0] + w4.y*zsh[q*4+1]
                 + w4.z*zsh[q*4+2] + w4.w*zsh[q*4+3];
        }
        float r = (f < 784) ? softplusf_(acc) : sigmoidf_(acc);
        g_smallw[m*SMALLF + f] = r * cf;
    }
}

// ================= K67: fused uncrop + k-reduction (sparse tanh) =================
__global__ void __launch_bounds__(256) k67_all(float* __restrict__ out)
{
    int blk = blockIdx.x;
    int b = blk >> 6;
    int tile = blk & 63;
    int t = threadIdx.x;
    __shared__ float ssx[KOBJ], sox[KOBJ], ssy[KOBJ], soy[KOBJ];
    if (t < KOBJ) {
        int m = t*BATCH + b;
        float bx = g_bxf[m], bw = g_bwf[m];
        float by = g_byf[m], bh = g_bhf[m];
        float sx = 28.0f / bw;
        float sy = 28.0f / bh;
        ssx[t] = sx;  sox[t] = (0.5f - bx + 0.5f*bw)*sx - 0.5f;
        ssy[t] = sy;  soy[t] = (0.5f - by + 0.5f*bh)*sy - 0.5f;
    }
    __syncthreads();

    int p = tile*256 + t;
    float Xf = (float)(p >> 7);
    float Yf = (float)(p & 127);

    float v[KOBJ];
    float s = 0.0f;
    #pragma unroll
    for (int k = 0; k < KOBJ; k++) {
        float x = Xf*ssx[k] + sox[k];
        float y = Yf*ssy[k] + soy[k];
        float w = 0.0f, im = 0.0f, tw = 0.0f;
        if (x > -1.0f && x < 28.0f && y > -1.0f && y < 28.0f) {
            float x0f = floorf(x), y0f = floorf(y);
            int x0 = (int)x0f, y0 = (int)y0f;
            float wx1 = x - x0f, wy1 = y - y0f;
            float wx0 = 1.0f - wx1, wy0 = 1.0f - wy1;
            bool xa = (x0 >= 0), xb = (x0+1 < 28);
            bool ya = (y0 >= 0), yb = (y0+1 < 28);
            float w00 = (xa&&ya) ? wx0*wy0 : 0.0f;
            float w10 = (xb&&ya) ? wx1*wy0 : 0.0f;
            float w01 = (xa&&yb) ? wx0*wy1 : 0.0f;
            float w11 = (xb&&yb) ? wx1*wy1 : 0.0f;
            const float* img = &g_smallw[(size_t)(k*BATCH+b)*SMALLF];
            int ix0 = min(max(x0,  0),27), ix1 = min(max(x0+1,0),27);
            int iy0 = min(max(y0,  0),27), iy1 = min(max(y0+1,0),27);
            int a00 = ix0*28+iy0, a10 = ix1*28+iy0, a01 = ix0*28+iy1, a11 = ix1*28+iy1;
            w  = w00*__ldg(&img[a00])     + w10*__ldg(&img[a10])
               + w01*__ldg(&img[a01])     + w11*__ldg(&img[a11]);
            im = w00*__ldg(&img[784+a00]) + w10*__ldg(&img[784+a10])
               + w01*__ldg(&img[784+a01]) + w11*__ldg(&img[784+a11]);
            tw = tanhf(w);
        }
        v[k] = w;
        s += w;
        out[OFF_BMNON + (size_t)(k*BATCH+b)*PIX + p] = tw;
        out[OFF_BIMG  + (size_t)(k*BATCH+b)*PIX + p] = im;
    }
    float ts = tanhf(s);
    float inv = 1.0f / fmaxf(s, 1e-6f);
    float f = ts * inv;
    #pragma unroll
    for (int k = 0; k < KOBJ; k++)
        out[OFF_BMASK + (size_t)(k*BATCH+b)*PIX + p] = v[k] * f;
}

// ================= launcher =================
extern "C" void kernel_launch(void* const* d_in, const int* in_sizes, int n_in,
                              void* d_out, int out_size)
{
    const float* logit = (const float*)d_in[0];
    const float* zmu   = (const float*)d_in[1];
    const float* zstd  = (const float*)d_in[2];
    const float* zeps  = (const float*)d_in[3];
    const float* epszi = (const float*)d_in[4];
    const float* feat  = (const float*)d_in[5];
    const float* wz    = (const float*)d_in[6];
    const float* bz    = (const float*)d_in[7];
    const float* wenc  = (const float*)d_in[8];
    const float* benc  = (const float*)d_in[9];
    const float* wdec  = (const float*)d_in[10];
    const float* bdec  = (const float*)d_in[11];
    float* out = (float*)d_out;

    cudaFuncSetAttribute(k4_fused, cudaFuncAttributeMaxDynamicSharedMemorySize, K4_SMEM);

    k1_site<<<32, 256>>>(logit, zmu, zstd, zeps, wz, bz, out);
    k2_topk<<<BATCH, 32>>>(out);
    dim3 g4(3, NSPLIT);
    k4_fused<<<g4, 256, K4_SMEM>>>(feat, wenc);
    k5_zi_dec<<<MTOT, 256>>>(epszi, wdec, bdec, benc, out);
    k67_all<<<BATCH*64, 256>>>(out);
}